// round 14
// baseline (speedup 1.0000x reference)
#include <cuda_runtime.h>
#include <cuda_fp16.h>
#include <cstdint>

#define UD 10000
#define ID 12000
#define IPAD 12032   // g_r pitch rows (94*128)
#define UPAD 10112   // g_l pitch rows (79*128)
#define IPAD2 12288  // item^T table pitch: 3*4096
#define UPAD2 10368  // user^T table pitch: 3*3456
#define NT3 7426     // 79*94 k3 tiles
#define G3 296       // k3 grid (2 per SM)

// ---------------- scratch ----------------
__device__ __align__(16) uint16_t g_iT_h[64 * IPAD2];                // item_sv^T fp16 [k][i]
__device__ __align__(16) uint16_t g_uT_h[64 * UPAD2];                // user_sv^T fp16 [k][u]
__device__ __align__(16) float    g_lp[3][(size_t)UD * 64];          // K1 partials [u][k]
__device__ __align__(16) float    g_rp[3][(size_t)ID * 64];          // K2 partials [i][k]
__device__ __align__(16) uint16_t g_l_h[UPAD * 64];                  // left*invL fp16 [u][k]
__device__ __align__(16) uint16_t g_r_h[IPAD * 64];                  // right^T fp16 [i][k]

// ---------------- helpers ----------------
__device__ __forceinline__ uint32_t smem_u32(const void* p) {
    uint32_t a;
    asm("{ .reg .u64 t; cvta.to.shared.u64 t, %1; cvt.u32.u64 %0, t; }" : "=r"(a) : "l"(p));
    return a;
}
__device__ __forceinline__ uint32_t packh2(float x0, float x1) {
    uint32_t r;
    asm("cvt.rn.f16x2.f32 %0, %1, %2;" : "=r"(r) : "f"(x1), "f"(x0));
    return r;
}
__device__ __forceinline__ void ldm4(uint32_t* r, uint32_t a) {
    asm volatile("ldmatrix.sync.aligned.m8n8.x4.shared.b16 {%0,%1,%2,%3},[%4];"
                 : "=r"(r[0]), "=r"(r[1]), "=r"(r[2]), "=r"(r[3]) : "r"(a));
}
__device__ __forceinline__ void ldm4t(uint32_t* r, uint32_t a) {
    asm volatile("ldmatrix.sync.aligned.m8n8.x4.trans.shared.b16 {%0,%1,%2,%3},[%4];"
                 : "=r"(r[0]), "=r"(r[1]), "=r"(r[2]), "=r"(r[3]) : "r"(a));
}
__device__ __forceinline__ void mma_f16(float* d, const uint32_t* a, uint32_t b0, uint32_t b1) {
    asm volatile("mma.sync.aligned.m16n8k16.row.col.f32.f16.f16.f32 "
                 "{%0,%1,%2,%3},{%4,%5,%6,%7},{%8,%9},{%0,%1,%2,%3};"
                 : "+f"(d[0]), "+f"(d[1]), "+f"(d[2]), "+f"(d[3])
                 : "r"(a[0]), "r"(a[1]), "r"(a[2]), "r"(a[3]), "r"(b0), "r"(b1));
}
#define CP16(dst, src) \
    asm volatile("cp.async.cg.shared.global [%0],[%1],16;" :: "r"(dst), "l"(src) : "memory")
#define CPCOMMIT() asm volatile("cp.async.commit_group;" ::: "memory")
#define CPWAIT0()  asm volatile("cp.async.wait_group 0;" ::: "memory")
#define CPWAIT1()  asm volatile("cp.async.wait_group 1;" ::: "memory")

// ---------------- prep: tiled transpose + fp16 ----------------
__global__ __launch_bounds__(256) void p_item(const float* __restrict__ isv) {
    __shared__ float st[64][65];
    const int t = threadIdx.x, i0 = blockIdx.x * 64;
#pragma unroll
    for (int q = 0; q < 16; q++) {
        int idx = t + q * 256;
        int il = idx >> 6, k = idx & 63, gi = i0 + il;
        st[il][k] = (gi < ID) ? isv[(size_t)gi * 64 + k] : 0.f;
    }
    __syncthreads();
#pragma unroll
    for (int q = 0; q < 16; q++) {
        int idx = t + q * 256;
        int k = idx >> 6, il = idx & 63;
        g_iT_h[(size_t)k * IPAD2 + i0 + il] = __half_as_ushort(__float2half_rn(st[il][k]));
    }
}
__global__ __launch_bounds__(256) void p_user(const float* __restrict__ usv) {
    __shared__ float st[64][65];
    const int t = threadIdx.x, u0 = blockIdx.x * 64;
#pragma unroll
    for (int q = 0; q < 16; q++) {
        int idx = t + q * 256;
        int ul = idx >> 6, k = idx & 63, gu = u0 + ul;
        st[ul][k] = (gu < UD) ? usv[(size_t)gu * 64 + k] : 0.f;
    }
    __syncthreads();
#pragma unroll
    for (int q = 0; q < 16; q++) {
        int idx = t + q * 256;
        int k = idx >> 6, ul = idx & 63;
        g_uT_h[(size_t)k * UPAD2 + u0 + ul] = __half_as_ushort(__float2half_rn(st[ul][k]));
    }
}

// ---------------- fused K1+K2, K-chunk 64, 2-buf, half-batch interleave ----------------
__global__ __launch_bounds__(256, 2) void k12_mma(const float* __restrict__ NA,
                                                  const float* __restrict__ Adj) {
    extern __shared__ __align__(16) char sm[];
    const int t = threadIdx.x, lane = t & 31, w = t >> 5;
    const uint32_t sb = smem_u32(sm);
    const int m0 = (w >> 1) * 32, n0 = (w & 1) * 32;
    const uint32_t boff = (uint32_t)(n0 + (lane & 15)) * 144 + ((lane >> 4) << 4);
    const int g = lane >> 2, tg = lane & 3;
    const int id = blockIdx.x;

    float acc[2][4][4];
#pragma unroll
    for (int a = 0; a < 2; a++)
#pragma unroll
        for (int b = 0; b < 4; b++)
#pragma unroll
            for (int cc = 0; cc < 4; cc++) acc[a][b][cc] = 0.f;

    float2 ar[8]; uint4 b4;

    if (id < 237) {
        const int tile = id % 79, split = id / 79;
        const int u0 = tile * 128, ibase0 = split * 4096;
        const uint32_t aoff = (uint32_t)(m0 + (lane & 15)) * 144 + ((lane >> 4) << 4);

        auto LDGf = [&](int c, int h) {
            const int ib = ibase0 + c * 64;
            const int ic2 = ((t & 15) << 1) + h * 32;
            const int gi = ib + ic2;
            const bool gok = gi < ID;
#pragma unroll
            for (int q = 0; q < 8; q++) {
                int gu = u0 + (t >> 4) + q * 16;
                ar[q] = (gok && gu < UD) ? *(const float2*)(NA + (size_t)gu * ID + gi)
                                         : make_float2(0.f, 0.f);
            }
            b4 = *(const uint4*)(g_iT_h + (size_t)(t >> 2) * IPAD2 + ib + ((t & 3) << 3) + h * 32);
        };
        auto STSf = [&](int b, int h) {
            char* ab = sm + b * 18432;
            const int ic2 = ((t & 15) << 1) + h * 32;
#pragma unroll
            for (int q = 0; q < 8; q++) {
                int row = (t >> 4) + q * 16;
                *(uint32_t*)(ab + row * 144 + ic2 * 2) = packh2(ar[q].x, ar[q].y);
            }
            *(uint4*)(sm + 36864 + b * 9216 + (t >> 2) * 144 + ((t & 3) << 4) + h * 64) = b4;
        };

        LDGf(0, 0); STSf(0, 0); LDGf(0, 1); STSf(0, 1);
        __syncthreads();

        for (int c = 0; c < 64; c++) {
            const int b = c & 1;
            const bool more = (c + 1 < 64);
            if (more) LDGf(c + 1, 0);
            const uint32_t bah = sb + b * 18432;
            const uint32_t bbh = sb + 36864 + b * 9216;
#pragma unroll
            for (int ks = 0; ks < 2; ks++) {
                uint32_t bh[2][4], ah[2][4];
#pragma unroll
                for (int p = 0; p < 2; p++)
                    ldm4(bh[p], bbh + boff + p * 2304 + ks * 32);
#pragma unroll
                for (int mi = 0; mi < 2; mi++)
                    ldm4(ah[mi], bah + aoff + mi * 2304 + ks * 32);
#pragma unroll
                for (int mi = 0; mi < 2; mi++)
#pragma unroll
                    for (int nt = 0; nt < 4; nt++) {
                        int p = nt >> 1, j = nt & 1;
                        mma_f16(acc[mi][nt], ah[mi], bh[p][j], bh[p][j + 2]);
                    }
            }
            if (more) { STSf(b ^ 1, 0); LDGf(c + 1, 1); }
#pragma unroll
            for (int ks = 2; ks < 4; ks++) {
                uint32_t bh[2][4], ah[2][4];
#pragma unroll
                for (int p = 0; p < 2; p++)
                    ldm4(bh[p], bbh + boff + p * 2304 + ks * 32);
#pragma unroll
                for (int mi = 0; mi < 2; mi++)
                    ldm4(ah[mi], bah + aoff + mi * 2304 + ks * 32);
#pragma unroll
                for (int mi = 0; mi < 2; mi++)
#pragma unroll
                    for (int nt = 0; nt < 4; nt++) {
                        int p = nt >> 1, j = nt & 1;
                        mma_f16(acc[mi][nt], ah[mi], bh[p][j], bh[p][j + 2]);
                    }
            }
            if (more) STSf(b ^ 1, 1);
            __syncthreads();
        }

        float* dst = g_lp[split];
#pragma unroll
        for (int mi = 0; mi < 2; mi++)
#pragma unroll
            for (int nt = 0; nt < 4; nt++) {
                int row = u0 + m0 + mi * 16 + g;
                int col = n0 + nt * 8 + tg * 2;
                if (row < UD)     *(float2*)(dst + (size_t)row * 64 + col)       = make_float2(acc[mi][nt][0], acc[mi][nt][1]);
                if (row + 8 < UD) *(float2*)(dst + (size_t)(row + 8) * 64 + col) = make_float2(acc[mi][nt][2], acc[mi][nt][3]);
            }
    } else {
        const int id2 = id - 237;
        const int tile = id2 % 94, split = id2 / 94;
        const int i0 = tile * 128, ubase0 = split * 3456;
        const uint32_t aofft = (uint32_t)((lane & 7) + ((lane >> 4) << 3)) * 272
                             + (uint32_t)(m0 + (((lane >> 3) & 1) << 3)) * 2;

        auto LDGf = [&](int c, int h) {
            const int ub = ubase0 + c * 64;
            const int i2 = (t & 63) << 1;
            const bool iok = (i0 + i2) < ID;
#pragma unroll
            for (int q = 0; q < 8; q++) {
                int gu = ub + (t >> 6) + q * 4 + h * 32;
                ar[q] = (iok && gu < UD) ? *(const float2*)(Adj + (size_t)gu * ID + i0 + i2)
                                         : make_float2(0.f, 0.f);
            }
            b4 = *(const uint4*)(g_uT_h + (size_t)(t >> 2) * UPAD2 + ub + ((t & 3) << 3) + h * 32);
        };
        auto STSf = [&](int b, int h) {
            char* ab = sm + b * 17408;
            const int i2 = (t & 63) << 1;
#pragma unroll
            for (int q = 0; q < 8; q++) {
                int aul = (t >> 6) + q * 4 + h * 32;
                *(uint32_t*)(ab + aul * 272 + i2 * 2) = packh2(ar[q].x, ar[q].y);
            }
            *(uint4*)(sm + 34816 + b * 9216 + (t >> 2) * 144 + ((t & 3) << 4) + h * 64) = b4;
        };

        LDGf(0, 0); STSf(0, 0); LDGf(0, 1); STSf(0, 1);
        __syncthreads();

        for (int c = 0; c < 54; c++) {
            const int b = c & 1;
            const bool more = (c + 1 < 54);
            if (more) LDGf(c + 1, 0);
            const uint32_t bah = sb + b * 17408;
            const uint32_t bbh = sb + 34816 + b * 9216;
#pragma unroll
            for (int ks = 0; ks < 2; ks++) {
                uint32_t bh[2][4], ah[2][4];
#pragma unroll
                for (int p = 0; p < 2; p++)
                    ldm4(bh[p], bbh + boff + p * 2304 + ks * 32);
#pragma unroll
                for (int mi = 0; mi < 2; mi++)
                    ldm4t(ah[mi], bah + aofft + mi * 32 + ks * 4352);
#pragma unroll
                for (int mi = 0; mi < 2; mi++)
#pragma unroll
                    for (int nt = 0; nt < 4; nt++) {
                        int p = nt >> 1, j = nt & 1;
                        mma_f16(acc[mi][nt], ah[mi], bh[p][j], bh[p][j + 2]);
                    }
            }
            if (more) { STSf(b ^ 1, 0); LDGf(c + 1, 1); }
#pragma unroll
            for (int ks = 2; ks < 4; ks++) {
                uint32_t bh[2][4], ah[2][4];
#pragma unroll
                for (int p = 0; p < 2; p++)
                    ldm4(bh[p], bbh + boff + p * 2304 + ks * 32);
#pragma unroll
                for (int mi = 0; mi < 2; mi++)
                    ldm4t(ah[mi], bah + aofft + mi * 32 + ks * 4352);
#pragma unroll
                for (int mi = 0; mi < 2; mi++)
#pragma unroll
                    for (int nt = 0; nt < 4; nt++) {
                        int p = nt >> 1, j = nt & 1;
                        mma_f16(acc[mi][nt], ah[mi], bh[p][j], bh[p][j + 2]);
                    }
            }
            if (more) STSf(b ^ 1, 1);
            __syncthreads();
        }

        float* dst = g_rp[split];
#pragma unroll
        for (int mi = 0; mi < 2; mi++)
#pragma unroll
            for (int nt = 0; nt < 4; nt++) {
                int row = i0 + m0 + mi * 16 + g;
                int col = n0 + nt * 8 + tg * 2;
                if (row < ID)     *(float2*)(dst + (size_t)row * 64 + col)       = make_float2(acc[mi][nt][0], acc[mi][nt][1]);
                if (row + 8 < ID) *(float2*)(dst + (size_t)(row + 8) * 64 + col) = make_float2(acc[mi][nt][2], acc[mi][nt][3]);
            }
    }
}

// ---------------- fused reductions + fp16 pack ----------------
__global__ __launch_bounds__(256) void red_lr(const float* __restrict__ lam) {
    int idx = blockIdx.x * 256 + threadIdx.x;
    if (idx < UPAD * 64) {
        int u = idx >> 6;
        float v = 0.f;
        if (u < UD) v = (g_lp[0][idx] + g_lp[1][idx] + g_lp[2][idx]) / lam[idx & 63];
        g_l_h[idx] = __half_as_ushort(__float2half_rn(v));
    } else {
        int idx2 = idx - UPAD * 64;
        if (idx2 >= IPAD * 64) return;
        int i = idx2 >> 6;
        float v = 0.f;
        if (i < ID) v = g_rp[0][idx2] + g_rp[1][idx2] + g_rp[2][idx2];
        g_r_h[idx2] = __half_as_ushort(__float2half_rn(v));
    }
}

// ---------------- K3: persistent CTAs, cross-tile double buffer ----------------
// smem 73728: buf b @ b*36864 { A(g_l) @0 (128x144), B(g_r) @18432 }
__global__ __launch_bounds__(256, 2) void k3_mma(float* __restrict__ out) {
    extern __shared__ __align__(16) char sm[];
    const int t = threadIdx.x, lane = t & 31, w = t >> 5;
    const uint32_t sb = smem_u32(sm);
    const int m0 = (w >> 2) * 64, n0 = (w & 3) * 32;
    const uint32_t abase = (uint32_t)(m0 + (lane & 15)) * 144 + ((lane >> 4) << 4);
    const uint32_t bbase = (uint32_t)(n0 + (lane & 15)) * 144 + ((lane >> 4) << 4);
    const int g = lane >> 2, tg = lane & 3;
    const int lrow = t >> 3, lc8 = (t & 7) << 3;   // loader: rows t>>3 + q*32, 8 halves at (t&7)*8

    auto CPA = [&](int b, int tile) {
        const int u0 = (tile / 94) * 128, i0 = (tile % 94) * 128;
        const uint32_t dstA = sb + b * 36864 + lrow * 144 + lc8 * 2;
        const uint32_t dstB = dstA + 18432;
#pragma unroll
        for (int q = 0; q < 4; q++) {
            int row = lrow + q * 32;
            CP16(dstA + q * 32 * 144, (const void*)(g_l_h + (size_t)(u0 + row) * 64 + lc8));
            CP16(dstB + q * 32 * 144, (const void*)(g_r_h + (size_t)(i0 + row) * 64 + lc8));
        }
        CPCOMMIT();
    };

    int tile = blockIdx.x;
    if (tile < NT3) CPA(0, tile);

    int b = 0;
    for (; tile < NT3; tile += G3, b ^= 1) {
        const int nxt = tile + G3;
        if (nxt < NT3) { CPA(b ^ 1, nxt); CPWAIT1(); } else { CPWAIT0(); }
        __syncthreads();

        const int u0 = (tile / 94) * 128, i0 = (tile % 94) * 128;
        const uint32_t ba = sb + b * 36864;
        const uint32_t bb = ba + 18432;

        float acc[4][4][4];
#pragma unroll
        for (int a = 0; a < 4; a++)
#pragma unroll
            for (int bb2 = 0; bb2 < 4; bb2++)
#pragma unroll
                for (int cc = 0; cc < 4; cc++) acc[a][bb2][cc] = 0.f;

#pragma unroll
        for (int ks = 0; ks < 4; ks++) {
            uint32_t bh[2][4];
#pragma unroll
            for (int p = 0; p < 2; p++)
                ldm4(bh[p], bb + bbase + p * 2304 + ks * 32);
#pragma unroll
            for (int mi = 0; mi < 4; mi++) {
                uint32_t ah[4];
                ldm4(ah, ba + abase + mi * 2304 + ks * 32);
#pragma unroll
                for (int nt = 0; nt < 4; nt++) {
                    int p = nt >> 1, j = nt & 1;
                    mma_f16(acc[mi][nt], ah, bh[p][j], bh[p][j + 2]);
                }
            }
        }

#pragma unroll
        for (int mi = 0; mi < 4; mi++)
#pragma unroll
            for (int nt = 0; nt < 4; nt++) {
                int row = u0 + m0 + mi * 16 + g;
                int col = i0 + n0 + nt * 8 + tg * 2;
                if (col < ID) {
                    if (row < UD)
                        __stcs((float2*)(out + (size_t)row * ID + col),
                               make_float2(acc[mi][nt][0], acc[mi][nt][1]));
                    if (row + 8 < UD)
                        __stcs((float2*)(out + (size_t)(row + 8) * ID + col),
                               make_float2(acc[mi][nt][2], acc[mi][nt][3]));
                }
            }
        __syncthreads();   // all warps done reading buf b before it is refilled
    }
}

// ---------------- launch ----------------
extern "C" void kernel_launch(void* const* d_in, const int* in_sizes, int n_in,
                              void* d_out, int out_size) {
    const float* lambda_mat = (const float*)d_in[0];
    const float* user_sv    = (const float*)d_in[1];
    const float* item_sv    = (const float*)d_in[2];
    const float* adj_mat    = (const float*)d_in[3];
    const float* norm_adj   = (const float*)d_in[4];
    float* out = (float*)d_out;

    cudaFuncSetAttribute(k12_mma, cudaFuncAttributeMaxDynamicSharedMemorySize, 55296);
    cudaFuncSetAttribute(k3_mma, cudaFuncAttributeMaxDynamicSharedMemorySize, 73728);

    p_item<<<IPAD2 / 64, 256>>>(item_sv);
    p_user<<<UPAD2 / 64, 256>>>(user_sv);
    k12_mma<<<237 + 282, 256, 55296>>>(norm_adj, adj_mat);
    red_lr<<<((UPAD + IPAD) * 64 + 255) / 256, 256>>>(lambda_mat);
    k3_mma<<<G3, 256, 73728>>>(out);
}

// round 15
// speedup vs baseline: 1.0077x; 1.0077x over previous
#include <cuda_runtime.h>
#include <cuda_fp16.h>
#include <cstdint>

#define UD 10000
#define ID 12000
#define IPAD 12032   // g_r pitch rows (94*128)
#define UPAD 10112   // g_l pitch rows (79*128)
#define IPAD2 12288  // item^T table pitch: 6*2048
#define UPAD2 10368  // user^T table pitch: 6*1728
#define NS 6         // split-K count per role
#define NK1 474      // 79*6 K1 CTAs
#define NK2 564      // 94*6 K2 CTAs

// ---------------- scratch ----------------
__device__ __align__(16) uint16_t g_iT_h[64 * IPAD2];                // item_sv^T fp16 [k][i]
__device__ __align__(16) uint16_t g_uT_h[64 * UPAD2];                // user_sv^T fp16 [k][u]
__device__ __align__(16) float    g_lp[NS][(size_t)UD * 64];         // K1 partials [u][k]
__device__ __align__(16) float    g_rp[NS][(size_t)ID * 64];         // K2 partials [i][k]
__device__ __align__(16) uint16_t g_l_h[UPAD * 64];                  // left*invL fp16 [u][k]
__device__ __align__(16) uint16_t g_r_h[IPAD * 64];                  // right^T fp16 [i][k]

// ---------------- helpers ----------------
__device__ __forceinline__ uint32_t smem_u32(const void* p) {
    uint32_t a;
    asm("{ .reg .u64 t; cvta.to.shared.u64 t, %1; cvt.u32.u64 %0, t; }" : "=r"(a) : "l"(p));
    return a;
}
__device__ __forceinline__ uint32_t packh2(float x0, float x1) {
    uint32_t r;
    asm("cvt.rn.f16x2.f32 %0, %1, %2;" : "=r"(r) : "f"(x1), "f"(x0));
    return r;
}
__device__ __forceinline__ void ldm4(uint32_t* r, uint32_t a) {
    asm volatile("ldmatrix.sync.aligned.m8n8.x4.shared.b16 {%0,%1,%2,%3},[%4];"
                 : "=r"(r[0]), "=r"(r[1]), "=r"(r[2]), "=r"(r[3]) : "r"(a));
}
__device__ __forceinline__ void ldm4t(uint32_t* r, uint32_t a) {
    asm volatile("ldmatrix.sync.aligned.m8n8.x4.trans.shared.b16 {%0,%1,%2,%3},[%4];"
                 : "=r"(r[0]), "=r"(r[1]), "=r"(r[2]), "=r"(r[3]) : "r"(a));
}
__device__ __forceinline__ void mma_f16(float* d, const uint32_t* a, uint32_t b0, uint32_t b1) {
    asm volatile("mma.sync.aligned.m16n8k16.row.col.f32.f16.f16.f32 "
                 "{%0,%1,%2,%3},{%4,%5,%6,%7},{%8,%9},{%0,%1,%2,%3};"
                 : "+f"(d[0]), "+f"(d[1]), "+f"(d[2]), "+f"(d[3])
                 : "r"(a[0]), "r"(a[1]), "r"(a[2]), "r"(a[3]), "r"(b0), "r"(b1));
}

// ---------------- prep: tiled transpose + fp16 ----------------
__global__ __launch_bounds__(256) void p_item(const float* __restrict__ isv) {
    __shared__ float st[64][65];
    const int t = threadIdx.x, i0 = blockIdx.x * 64;
#pragma unroll
    for (int q = 0; q < 16; q++) {
        int idx = t + q * 256;
        int il = idx >> 6, k = idx & 63, gi = i0 + il;
        st[il][k] = (gi < ID) ? isv[(size_t)gi * 64 + k] : 0.f;
    }
    __syncthreads();
#pragma unroll
    for (int q = 0; q < 16; q++) {
        int idx = t + q * 256;
        int k = idx >> 6, il = idx & 63;
        g_iT_h[(size_t)k * IPAD2 + i0 + il] = __half_as_ushort(__float2half_rn(st[il][k]));
    }
}
__global__ __launch_bounds__(256) void p_user(const float* __restrict__ usv) {
    __shared__ float st[64][65];
    const int t = threadIdx.x, u0 = blockIdx.x * 64;
#pragma unroll
    for (int q = 0; q < 16; q++) {
        int idx = t + q * 256;
        int ul = idx >> 6, k = idx & 63, gu = u0 + ul;
        st[ul][k] = (gu < UD) ? usv[(size_t)gu * 64 + k] : 0.f;
    }
    __syncthreads();
#pragma unroll
    for (int q = 0; q < 16; q++) {
        int idx = t + q * 256;
        int k = idx >> 6, ul = idx & 63;
        g_uT_h[(size_t)k * UPAD2 + u0 + ul] = __half_as_ushort(__float2half_rn(st[ul][k]));
    }
}

// ---------------- fused K1+K2, K-chunk 64, 2-buf, 6-way split-K ----------------
// CTA 0..473   : K1  (tile=id%79,  split=id/79)   span 2048 -> 32 chunks of 64 i
// CTA 474..1037: K2  (tile=id2%94, split=id2/94)  span 1728 -> 27 chunks of 64 u
__global__ __launch_bounds__(256, 2) void k12_mma(const float* __restrict__ NA,
                                                  const float* __restrict__ Adj) {
    extern __shared__ __align__(16) char sm[];
    const int t = threadIdx.x, lane = t & 31, w = t >> 5;
    const uint32_t sb = smem_u32(sm);
    const int m0 = (w >> 1) * 32, n0 = (w & 1) * 32;
    const uint32_t boff = (uint32_t)(n0 + (lane & 15)) * 144 + ((lane >> 4) << 4);
    const int g = lane >> 2, tg = lane & 3;
    const int id = blockIdx.x;

    float acc[2][4][4];
#pragma unroll
    for (int a = 0; a < 2; a++)
#pragma unroll
        for (int b = 0; b < 4; b++)
#pragma unroll
            for (int cc = 0; cc < 4; cc++) acc[a][b][cc] = 0.f;

    float2 ar[8]; uint4 b4;

    if (id < NK1) {
        const int tile = id % 79, split = id / 79;
        const int u0 = tile * 128, ibase0 = split * 2048;
        const uint32_t aoff = (uint32_t)(m0 + (lane & 15)) * 144 + ((lane >> 4) << 4);

        auto LDGf = [&](int c, int h) {
            const int ib = ibase0 + c * 64;
            const int ic2 = ((t & 15) << 1) + h * 32;
            const int gi = ib + ic2;
            const bool gok = gi < ID;
#pragma unroll
            for (int q = 0; q < 8; q++) {
                int gu = u0 + (t >> 4) + q * 16;
                ar[q] = (gok && gu < UD) ? *(const float2*)(NA + (size_t)gu * ID + gi)
                                         : make_float2(0.f, 0.f);
            }
            b4 = *(const uint4*)(g_iT_h + (size_t)(t >> 2) * IPAD2 + ib + ((t & 3) << 3) + h * 32);
        };
        auto STSf = [&](int b, int h) {
            char* ab = sm + b * 18432;
            const int ic2 = ((t & 15) << 1) + h * 32;
#pragma unroll
            for (int q = 0; q < 8; q++) {
                int row = (t >> 4) + q * 16;
                *(uint32_t*)(ab + row * 144 + ic2 * 2) = packh2(ar[q].x, ar[q].y);
            }
            *(uint4*)(sm + 36864 + b * 9216 + (t >> 2) * 144 + ((t & 3) << 4) + h * 64) = b4;
        };

        LDGf(0, 0); STSf(0, 0); LDGf(0, 1); STSf(0, 1);
        __syncthreads();

        for (int c = 0; c < 32; c++) {
            const int b = c & 1;
            const bool more = (c + 1 < 32);
            if (more) LDGf(c + 1, 0);
            const uint32_t bah = sb + b * 18432;
            const uint32_t bbh = sb + 36864 + b * 9216;
#pragma unroll
            for (int ks = 0; ks < 2; ks++) {
                uint32_t bh[2][4], ah[2][4];
#pragma unroll
                for (int p = 0; p < 2; p++)
                    ldm4(bh[p], bbh + boff + p * 2304 + ks * 32);
#pragma unroll
                for (int mi = 0; mi < 2; mi++)
                    ldm4(ah[mi], bah + aoff + mi * 2304 + ks * 32);
#pragma unroll
                for (int mi = 0; mi < 2; mi++)
#pragma unroll
                    for (int nt = 0; nt < 4; nt++) {
                        int p = nt >> 1, j = nt & 1;
                        mma_f16(acc[mi][nt], ah[mi], bh[p][j], bh[p][j + 2]);
                    }
            }
            if (more) { STSf(b ^ 1, 0); LDGf(c + 1, 1); }
#pragma unroll
            for (int ks = 2; ks < 4; ks++) {
                uint32_t bh[2][4], ah[2][4];
#pragma unroll
                for (int p = 0; p < 2; p++)
                    ldm4(bh[p], bbh + boff + p * 2304 + ks * 32);
#pragma unroll
                for (int mi = 0; mi < 2; mi++)
                    ldm4(ah[mi], bah + aoff + mi * 2304 + ks * 32);
#pragma unroll
                for (int mi = 0; mi < 2; mi++)
#pragma unroll
                    for (int nt = 0; nt < 4; nt++) {
                        int p = nt >> 1, j = nt & 1;
                        mma_f16(acc[mi][nt], ah[mi], bh[p][j], bh[p][j + 2]);
                    }
            }
            if (more) STSf(b ^ 1, 1);
            __syncthreads();
        }

        float* dst = g_lp[split];
#pragma unroll
        for (int mi = 0; mi < 2; mi++)
#pragma unroll
            for (int nt = 0; nt < 4; nt++) {
                int row = u0 + m0 + mi * 16 + g;
                int col = n0 + nt * 8 + tg * 2;
                if (row < UD)     *(float2*)(dst + (size_t)row * 64 + col)       = make_float2(acc[mi][nt][0], acc[mi][nt][1]);
                if (row + 8 < UD) *(float2*)(dst + (size_t)(row + 8) * 64 + col) = make_float2(acc[mi][nt][2], acc[mi][nt][3]);
            }
    } else {
        const int id2 = id - NK1;
        const int tile = id2 % 94, split = id2 / 94;
        const int i0 = tile * 128, ubase0 = split * 1728;
        const uint32_t aofft = (uint32_t)((lane & 7) + ((lane >> 4) << 3)) * 272
                             + (uint32_t)(m0 + (((lane >> 3) & 1) << 3)) * 2;

        auto LDGf = [&](int c, int h) {
            const int ub = ubase0 + c * 64;
            const int i2 = (t & 63) << 1;
            const bool iok = (i0 + i2) < ID;
#pragma unroll
            for (int q = 0; q < 8; q++) {
                int gu = ub + (t >> 6) + q * 4 + h * 32;
                ar[q] = (iok && gu < UD) ? *(const float2*)(Adj + (size_t)gu * ID + i0 + i2)
                                         : make_float2(0.f, 0.f);
            }
            b4 = *(const uint4*)(g_uT_h + (size_t)(t >> 2) * UPAD2 + ub + ((t & 3) << 3) + h * 32);
        };
        auto STSf = [&](int b, int h) {
            char* ab = sm + b * 17408;
            const int i2 = (t & 63) << 1;
#pragma unroll
            for (int q = 0; q < 8; q++) {
                int aul = (t >> 6) + q * 4 + h * 32;
                *(uint32_t*)(ab + aul * 272 + i2 * 2) = packh2(ar[q].x, ar[q].y);
            }
            *(uint4*)(sm + 34816 + b * 9216 + (t >> 2) * 144 + ((t & 3) << 4) + h * 64) = b4;
        };

        LDGf(0, 0); STSf(0, 0); LDGf(0, 1); STSf(0, 1);
        __syncthreads();

        for (int c = 0; c < 27; c++) {
            const int b = c & 1;
            const bool more = (c + 1 < 27);
            if (more) LDGf(c + 1, 0);
            const uint32_t bah = sb + b * 17408;
            const uint32_t bbh = sb + 34816 + b * 9216;
#pragma unroll
            for (int ks = 0; ks < 2; ks++) {
                uint32_t bh[2][4], ah[2][4];
#pragma unroll
                for (int p = 0; p < 2; p++)
                    ldm4(bh[p], bbh + boff + p * 2304 + ks * 32);
#pragma unroll
                for (int mi = 0; mi < 2; mi++)
                    ldm4t(ah[mi], bah + aofft + mi * 32 + ks * 4352);
#pragma unroll
                for (int mi = 0; mi < 2; mi++)
#pragma unroll
                    for (int nt = 0; nt < 4; nt++) {
                        int p = nt >> 1, j = nt & 1;
                        mma_f16(acc[mi][nt], ah[mi], bh[p][j], bh[p][j + 2]);
                    }
            }
            if (more) { STSf(b ^ 1, 0); LDGf(c + 1, 1); }
#pragma unroll
            for (int ks = 2; ks < 4; ks++) {
                uint32_t bh[2][4], ah[2][4];
#pragma unroll
                for (int p = 0; p < 2; p++)
                    ldm4(bh[p], bbh + boff + p * 2304 + ks * 32);
#pragma unroll
                for (int mi = 0; mi < 2; mi++)
                    ldm4t(ah[mi], bah + aofft + mi * 32 + ks * 4352);
#pragma unroll
                for (int mi = 0; mi < 2; mi++)
#pragma unroll
                    for (int nt = 0; nt < 4; nt++) {
                        int p = nt >> 1, j = nt & 1;
                        mma_f16(acc[mi][nt], ah[mi], bh[p][j], bh[p][j + 2]);
                    }
            }
            if (more) STSf(b ^ 1, 1);
            __syncthreads();
        }

        float* dst = g_rp[split];
#pragma unroll
        for (int mi = 0; mi < 2; mi++)
#pragma unroll
            for (int nt = 0; nt < 4; nt++) {
                int row = i0 + m0 + mi * 16 + g;
                int col = n0 + nt * 8 + tg * 2;
                if (row < ID)     *(float2*)(dst + (size_t)row * 64 + col)       = make_float2(acc[mi][nt][0], acc[mi][nt][1]);
                if (row + 8 < ID) *(float2*)(dst + (size_t)(row + 8) * 64 + col) = make_float2(acc[mi][nt][2], acc[mi][nt][3]);
            }
    }
}

// ---------------- fused reductions + fp16 pack ----------------
__global__ __launch_bounds__(256) void red_lr(const float* __restrict__ lam) {
    int idx = blockIdx.x * 256 + threadIdx.x;
    if (idx < UPAD * 64) {
        int u = idx >> 6;
        float v = 0.f;
        if (u < UD) {
            v = g_lp[0][idx];
#pragma unroll
            for (int s = 1; s < NS; s++) v += g_lp[s][idx];
            v /= lam[idx & 63];
        }
        g_l_h[idx] = __half_as_ushort(__float2half_rn(v));
    } else {
        int idx2 = idx - UPAD * 64;
        if (idx2 >= IPAD * 64) return;
        int i = idx2 >> 6;
        float v = 0.f;
        if (i < ID) {
            v = g_rp[0][idx2];
#pragma unroll
            for (int s = 1; s < NS; s++) v += g_rp[s][idx2];
        }
        g_r_h[idx2] = __half_as_ushort(__float2half_rn(v));
    }
}

// ---------------- K3: out[u][i] = g_l @ g_r^T  (M=128u, N=128i, K=64, single pass) ---------------
__global__ __launch_bounds__(256, 2) void k3_mma(float* __restrict__ out) {
    extern __shared__ __align__(16) char sm[];
    const int t = threadIdx.x, lane = t & 31, w = t >> 5;
    const uint32_t sb = smem_u32(sm);
    const int u0 = blockIdx.x * 128, i0 = blockIdx.y * 128;
    const int m0 = (w >> 2) * 64, n0 = (w & 3) * 32;
    const uint32_t abase = (uint32_t)(m0 + (lane & 15)) * 144 + ((lane >> 4) << 4);
    const uint32_t bbase = (uint32_t)(n0 + (lane & 15)) * 144 + ((lane >> 4) << 4);

#pragma unroll
    for (int q = 0; q < 4; q++) {
        int idx = t + q * 256;
        int row = idx >> 3, c8 = (idx & 7) << 3;
        *(uint4*)(sm + row * 144 + c8 * 2)         = *(const uint4*)(g_l_h + (size_t)(u0 + row) * 64 + c8);
        *(uint4*)(sm + 18432 + row * 144 + c8 * 2) = *(const uint4*)(g_r_h + (size_t)(i0 + row) * 64 + c8);
    }
    __syncthreads();

    float acc[4][4][4];
#pragma unroll
    for (int a = 0; a < 4; a++)
#pragma unroll
        for (int b = 0; b < 4; b++)
#pragma unroll
            for (int cc = 0; cc < 4; cc++) acc[a][b][cc] = 0.f;

#pragma unroll
    for (int ks = 0; ks < 4; ks++) {
        uint32_t bh[2][4];
#pragma unroll
        for (int p = 0; p < 2; p++)
            ldm4(bh[p], sb + 18432 + bbase + p * 2304 + ks * 32);
#pragma unroll
        for (int mi = 0; mi < 4; mi++) {
            uint32_t ah[4];
            ldm4(ah, sb + abase + mi * 2304 + ks * 32);
#pragma unroll
            for (int nt = 0; nt < 4; nt++) {
                int p = nt >> 1, j = nt & 1;
                mma_f16(acc[mi][nt], ah, bh[p][j], bh[p][j + 2]);
            }
        }
    }

    const int g = lane >> 2, tg = lane & 3;
#pragma unroll
    for (int mi = 0; mi < 4; mi++)
#pragma unroll
        for (int nt = 0; nt < 4; nt++) {
            int row = u0 + m0 + mi * 16 + g;
            int col = i0 + n0 + nt * 8 + tg * 2;
            if (col < ID) {
                if (row < UD)
                    __stcs((float2*)(out + (size_t)row * ID + col),
                           make_float2(acc[mi][nt][0], acc[mi][nt][1]));
                if (row + 8 < UD)
                    __stcs((float2*)(out + (size_t)(row + 8) * ID + col),
                           make_float2(acc[mi][nt][2], acc[mi][nt][3]));
            }
        }
}

// ---------------- launch ----------------
extern "C" void kernel_launch(void* const* d_in, const int* in_sizes, int n_in,
                              void* d_out, int out_size) {
    const float* lambda_mat = (const float*)d_in[0];
    const float* user_sv    = (const float*)d_in[1];
    const float* item_sv    = (const float*)d_in[2];
    const float* adj_mat    = (const float*)d_in[3];
    const float* norm_adj   = (const float*)d_in[4];
    float* out = (float*)d_out;

    cudaFuncSetAttribute(k12_mma, cudaFuncAttributeMaxDynamicSharedMemorySize, 55296);
    cudaFuncSetAttribute(k3_mma, cudaFuncAttributeMaxDynamicSharedMemorySize, 36864);

    p_item<<<IPAD2 / 64, 256>>>(item_sv);
    p_user<<<UPAD2 / 64, 256>>>(user_sv);
    k12_mma<<<NK1 + NK2, 256, 55296>>>(norm_adj, adj_mat);
    red_lr<<<((UPAD + IPAD) * 64 + 255) / 256, 256>>>(lambda_mat);
    k3_mma<<<dim3(79, 94), 256, 36864>>>(out);
}

// round 16
// speedup vs baseline: 1.0173x; 1.0096x over previous
#include <cuda_runtime.h>
#include <cuda_fp16.h>
#include <cstdint>

#define UD 10000
#define ID 12000
#define IPAD 12032   // g_r pitch rows (94*128)
#define UPAD 10112   // g_l pitch rows (79*128)
#define IPAD2 12288  // item^T table pitch: 3*4096
#define UPAD2 10368  // user^T table pitch: 3*3456

// ---------------- scratch ----------------
__device__ __align__(16) uint16_t g_iT_h[64 * IPAD2];                // item_sv^T fp16 [k][i]
__device__ __align__(16) uint16_t g_uT_h[64 * UPAD2];                // user_sv^T fp16 [k][u]
__device__ __align__(16) float    g_lp[3][(size_t)UD * 64];          // K1 partials [u][k]
__device__ __align__(16) float    g_rp[3][(size_t)ID * 64];          // K2 partials [i][k]
__device__ __align__(16) uint16_t g_l_h[UPAD * 64];                  // left*invL fp16 [u][k]
__device__ __align__(16) uint16_t g_r_h[IPAD * 64];                  // right^T fp16 [i][k]

// ---------------- helpers ----------------
__device__ __forceinline__ uint32_t smem_u32(const void* p) {
    uint32_t a;
    asm("{ .reg .u64 t; cvta.to.shared.u64 t, %1; cvt.u32.u64 %0, t; }" : "=r"(a) : "l"(p));
    return a;
}
__device__ __forceinline__ uint32_t packh2(float x0, float x1) {
    uint32_t r;
    asm("cvt.rn.f16x2.f32 %0, %1, %2;" : "=r"(r) : "f"(x1), "f"(x0));
    return r;
}
__device__ __forceinline__ void ldm4(uint32_t* r, uint32_t a) {
    asm volatile("ldmatrix.sync.aligned.m8n8.x4.shared.b16 {%0,%1,%2,%3},[%4];"
                 : "=r"(r[0]), "=r"(r[1]), "=r"(r[2]), "=r"(r[3]) : "r"(a));
}
__device__ __forceinline__ void ldm4t(uint32_t* r, uint32_t a) {
    asm volatile("ldmatrix.sync.aligned.m8n8.x4.trans.shared.b16 {%0,%1,%2,%3},[%4];"
                 : "=r"(r[0]), "=r"(r[1]), "=r"(r[2]), "=r"(r[3]) : "r"(a));
}
__device__ __forceinline__ void mma_f16(float* d, const uint32_t* a, uint32_t b0, uint32_t b1) {
    asm volatile("mma.sync.aligned.m16n8k16.row.col.f32.f16.f16.f32 "
                 "{%0,%1,%2,%3},{%4,%5,%6,%7},{%8,%9},{%0,%1,%2,%3};"
                 : "+f"(d[0]), "+f"(d[1]), "+f"(d[2]), "+f"(d[3])
                 : "r"(a[0]), "r"(a[1]), "r"(a[2]), "r"(a[3]), "r"(b0), "r"(b1));
}

// ---------------- prep: tiled transpose + fp16 ----------------
__global__ __launch_bounds__(256) void p_item(const float* __restrict__ isv) {
    __shared__ float st[64][65];
    const int t = threadIdx.x, i0 = blockIdx.x * 64;
#pragma unroll
    for (int q = 0; q < 16; q++) {
        int idx = t + q * 256;
        int il = idx >> 6, k = idx & 63, gi = i0 + il;
        st[il][k] = (gi < ID) ? isv[(size_t)gi * 64 + k] : 0.f;
    }
    __syncthreads();
#pragma unroll
    for (int q = 0; q < 16; q++) {
        int idx = t + q * 256;
        int k = idx >> 6, il = idx & 63;
        g_iT_h[(size_t)k * IPAD2 + i0 + il] = __half_as_ushort(__float2half_rn(st[il][k]));
    }
}
__global__ __launch_bounds__(256) void p_user(const float* __restrict__ usv) {
    __shared__ float st[64][65];
    const int t = threadIdx.x, u0 = blockIdx.x * 64;
#pragma unroll
    for (int q = 0; q < 16; q++) {
        int idx = t + q * 256;
        int ul = idx >> 6, k = idx & 63, gu = u0 + ul;
        st[ul][k] = (gu < UD) ? usv[(size_t)gu * 64 + k] : 0.f;
    }
    __syncthreads();
#pragma unroll
    for (int q = 0; q < 16; q++) {
        int idx = t + q * 256;
        int k = idx >> 6, ul = idx & 63;
        g_uT_h[(size_t)k * UPAD2 + u0 + ul] = __half_as_ushort(__float2half_rn(st[ul][k]));
    }
}

// ---------------- fused K1+K2, K-chunk 64, 2-buf, half-batch interleave (R13 exact) --------------
__global__ __launch_bounds__(256, 2) void k12_mma(const float* __restrict__ NA,
                                                  const float* __restrict__ Adj) {
    extern __shared__ __align__(16) char sm[];
    const int t = threadIdx.x, lane = t & 31, w = t >> 5;
    const uint32_t sb = smem_u32(sm);
    const int m0 = (w >> 1) * 32, n0 = (w & 1) * 32;
    const uint32_t boff = (uint32_t)(n0 + (lane & 15)) * 144 + ((lane >> 4) << 4);
    const int g = lane >> 2, tg = lane & 3;
    const int id = blockIdx.x;

    float acc[2][4][4];
#pragma unroll
    for (int a = 0; a < 2; a++)
#pragma unroll
        for (int b = 0; b < 4; b++)
#pragma unroll
            for (int cc = 0; cc < 4; cc++) acc[a][b][cc] = 0.f;

    float2 ar[8]; uint4 b4;

    if (id < 237) {
        const int tile = id % 79, split = id / 79;
        const int u0 = tile * 128, ibase0 = split * 4096;
        const uint32_t aoff = (uint32_t)(m0 + (lane & 15)) * 144 + ((lane >> 4) << 4);

        auto LDGf = [&](int c, int h) {
            const int ib = ibase0 + c * 64;
            const int ic2 = ((t & 15) << 1) + h * 32;
            const int gi = ib + ic2;
            const bool gok = gi < ID;
#pragma unroll
            for (int q = 0; q < 8; q++) {
                int gu = u0 + (t >> 4) + q * 16;
                ar[q] = (gok && gu < UD) ? *(const float2*)(NA + (size_t)gu * ID + gi)
                                         : make_float2(0.f, 0.f);
            }
            b4 = *(const uint4*)(g_iT_h + (size_t)(t >> 2) * IPAD2 + ib + ((t & 3) << 3) + h * 32);
        };
        auto STSf = [&](int b, int h) {
            char* ab = sm + b * 18432;
            const int ic2 = ((t & 15) << 1) + h * 32;
#pragma unroll
            for (int q = 0; q < 8; q++) {
                int row = (t >> 4) + q * 16;
                *(uint32_t*)(ab + row * 144 + ic2 * 2) = packh2(ar[q].x, ar[q].y);
            }
            *(uint4*)(sm + 36864 + b * 9216 + (t >> 2) * 144 + ((t & 3) << 4) + h * 64) = b4;
        };

        LDGf(0, 0); STSf(0, 0); LDGf(0, 1); STSf(0, 1);
        __syncthreads();

        for (int c = 0; c < 64; c++) {
            const int b = c & 1;
            const bool more = (c + 1 < 64);
            if (more) LDGf(c + 1, 0);
            const uint32_t bah = sb + b * 18432;
            const uint32_t bbh = sb + 36864 + b * 9216;
#pragma unroll
            for (int ks = 0; ks < 2; ks++) {
                uint32_t bh[2][4], ah[2][4];
#pragma unroll
                for (int p = 0; p < 2; p++)
                    ldm4(bh[p], bbh + boff + p * 2304 + ks * 32);
#pragma unroll
                for (int mi = 0; mi < 2; mi++)
                    ldm4(ah[mi], bah + aoff + mi * 2304 + ks * 32);
#pragma unroll
                for (int mi = 0; mi < 2; mi++)
#pragma unroll
                    for (int nt = 0; nt < 4; nt++) {
                        int p = nt >> 1, j = nt & 1;
                        mma_f16(acc[mi][nt], ah[mi], bh[p][j], bh[p][j + 2]);
                    }
            }
            if (more) { STSf(b ^ 1, 0); LDGf(c + 1, 1); }
#pragma unroll
            for (int ks = 2; ks < 4; ks++) {
                uint32_t bh[2][4], ah[2][4];
#pragma unroll
                for (int p = 0; p < 2; p++)
                    ldm4(bh[p], bbh + boff + p * 2304 + ks * 32);
#pragma unroll
                for (int mi = 0; mi < 2; mi++)
                    ldm4(ah[mi], bah + aoff + mi * 2304 + ks * 32);
#pragma unroll
                for (int mi = 0; mi < 2; mi++)
#pragma unroll
                    for (int nt = 0; nt < 4; nt++) {
                        int p = nt >> 1, j = nt & 1;
                        mma_f16(acc[mi][nt], ah[mi], bh[p][j], bh[p][j + 2]);
                    }
            }
            if (more) STSf(b ^ 1, 1);
            __syncthreads();
        }

        float* dst = g_lp[split];
#pragma unroll
        for (int mi = 0; mi < 2; mi++)
#pragma unroll
            for (int nt = 0; nt < 4; nt++) {
                int row = u0 + m0 + mi * 16 + g;
                int col = n0 + nt * 8 + tg * 2;
                if (row < UD)     *(float2*)(dst + (size_t)row * 64 + col)       = make_float2(acc[mi][nt][0], acc[mi][nt][1]);
                if (row + 8 < UD) *(float2*)(dst + (size_t)(row + 8) * 64 + col) = make_float2(acc[mi][nt][2], acc[mi][nt][3]);
            }
    } else {
        const int id2 = id - 237;
        const int tile = id2 % 94, split = id2 / 94;
        const int i0 = tile * 128, ubase0 = split * 3456;
        const uint32_t aofft = (uint32_t)((lane & 7) + ((lane >> 4) << 3)) * 272
                             + (uint32_t)(m0 + (((lane >> 3) & 1) << 3)) * 2;

        auto LDGf = [&](int c, int h) {
            const int ub = ubase0 + c * 64;
            const int i2 = (t & 63) << 1;
            const bool iok = (i0 + i2) < ID;
#pragma unroll
            for (int q = 0; q < 8; q++) {
                int gu = ub + (t >> 6) + q * 4 + h * 32;
                ar[q] = (iok && gu < UD) ? *(const float2*)(Adj + (size_t)gu * ID + i0 + i2)
                                         : make_float2(0.f, 0.f);
            }
            b4 = *(const uint4*)(g_uT_h + (size_t)(t >> 2) * UPAD2 + ub + ((t & 3) << 3) + h * 32);
        };
        auto STSf = [&](int b, int h) {
            char* ab = sm + b * 17408;
            const int i2 = (t & 63) << 1;
#pragma unroll
            for (int q = 0; q < 8; q++) {
                int aul = (t >> 6) + q * 4 + h * 32;
                *(uint32_t*)(ab + aul * 272 + i2 * 2) = packh2(ar[q].x, ar[q].y);
            }
            *(uint4*)(sm + 34816 + b * 9216 + (t >> 2) * 144 + ((t & 3) << 4) + h * 64) = b4;
        };

        LDGf(0, 0); STSf(0, 0); LDGf(0, 1); STSf(0, 1);
        __syncthreads();

        for (int c = 0; c < 54; c++) {
            const int b = c & 1;
            const bool more = (c + 1 < 54);
            if (more) LDGf(c + 1, 0);
            const uint32_t bah = sb + b * 17408;
            const uint32_t bbh = sb + 34816 + b * 9216;
#pragma unroll
            for (int ks = 0; ks < 2; ks++) {
                uint32_t bh[2][4], ah[2][4];
#pragma unroll
                for (int p = 0; p < 2; p++)
                    ldm4(bh[p], bbh + boff + p * 2304 + ks * 32);
#pragma unroll
                for (int mi = 0; mi < 2; mi++)
                    ldm4t(ah[mi], bah + aofft + mi * 32 + ks * 4352);
#pragma unroll
                for (int mi = 0; mi < 2; mi++)
#pragma unroll
                    for (int nt = 0; nt < 4; nt++) {
                        int p = nt >> 1, j = nt & 1;
                        mma_f16(acc[mi][nt], ah[mi], bh[p][j], bh[p][j + 2]);
                    }
            }
            if (more) { STSf(b ^ 1, 0); LDGf(c + 1, 1); }
#pragma unroll
            for (int ks = 2; ks < 4; ks++) {
                uint32_t bh[2][4], ah[2][4];
#pragma unroll
                for (int p = 0; p < 2; p++)
                    ldm4(bh[p], bbh + boff + p * 2304 + ks * 32);
#pragma unroll
                for (int mi = 0; mi < 2; mi++)
                    ldm4t(ah[mi], bah + aofft + mi * 32 + ks * 4352);
#pragma unroll
                for (int mi = 0; mi < 2; mi++)
#pragma unroll
                    for (int nt = 0; nt < 4; nt++) {
                        int p = nt >> 1, j = nt & 1;
                        mma_f16(acc[mi][nt], ah[mi], bh[p][j], bh[p][j + 2]);
                    }
            }
            if (more) STSf(b ^ 1, 1);
            __syncthreads();
        }

        float* dst = g_rp[split];
#pragma unroll
        for (int mi = 0; mi < 2; mi++)
#pragma unroll
            for (int nt = 0; nt < 4; nt++) {
                int row = i0 + m0 + mi * 16 + g;
                int col = n0 + nt * 8 + tg * 2;
                if (row < ID)     *(float2*)(dst + (size_t)row * 64 + col)       = make_float2(acc[mi][nt][0], acc[mi][nt][1]);
                if (row + 8 < ID) *(float2*)(dst + (size_t)(row + 8) * 64 + col) = make_float2(acc[mi][nt][2], acc[mi][nt][3]);
            }
    }
}

// ---------------- fused reductions + fp16 pack ----------------
__global__ __launch_bounds__(256) void red_lr(const float* __restrict__ lam) {
    int idx = blockIdx.x * 256 + threadIdx.x;
    if (idx < UPAD * 64) {
        int u = idx >> 6;
        float v = 0.f;
        if (u < UD) v = (g_lp[0][idx] + g_lp[1][idx] + g_lp[2][idx]) / lam[idx & 63];
        g_l_h[idx] = __half_as_ushort(__float2half_rn(v));
    } else {
        int idx2 = idx - UPAD * 64;
        if (idx2 >= IPAD * 64) return;
        int i = idx2 >> 6;
        float v = 0.f;
        if (i < ID) v = g_rp[0][idx2] + g_rp[1][idx2] + g_rp[2][idx2];
        g_r_h[idx2] = __half_as_ushort(__float2half_rn(v));
    }
}

// ---------------- K3: out[u][i] = g_l @ g_r^T  (M=128u, N=128i, K=64, staged float4 epilogue) ----
// dyn smem 69632: operands A @0 (128x144), B @18432; epilogue reuses sm as fp32 tile pitch 544
__global__ __launch_bounds__(256, 2) void k3_mma(float* __restrict__ out) {
    extern __shared__ __align__(16) char sm[];
    const int t = threadIdx.x, lane = t & 31, w = t >> 5;
    const uint32_t sb = smem_u32(sm);
    const int u0 = blockIdx.x * 128, i0 = blockIdx.y * 128;
    const int m0 = (w >> 2) * 64, n0 = (w & 3) * 32;
    const uint32_t abase = (uint32_t)(m0 + (lane & 15)) * 144 + ((lane >> 4) << 4);
    const uint32_t bbase = (uint32_t)(n0 + (lane & 15)) * 144 + ((lane >> 4) << 4);

#pragma unroll
    for (int q = 0; q < 4; q++) {
        int idx = t + q * 256;
        int row = idx >> 3, c8 = (idx & 7) << 3;
        *(uint4*)(sm + row * 144 + c8 * 2)         = *(const uint4*)(g_l_h + (size_t)(u0 + row) * 64 + c8);
        *(uint4*)(sm + 18432 + row * 144 + c8 * 2) = *(const uint4*)(g_r_h + (size_t)(i0 + row) * 64 + c8);
    }
    __syncthreads();

    float acc[4][4][4];
#pragma unroll
    for (int a = 0; a < 4; a++)
#pragma unroll
        for (int b = 0; b < 4; b++)
#pragma unroll
            for (int cc = 0; cc < 4; cc++) acc[a][b][cc] = 0.f;

#pragma unroll
    for (int ks = 0; ks < 4; ks++) {
        uint32_t bh[2][4];
#pragma unroll
        for (int p = 0; p < 2; p++)
            ldm4(bh[p], sb + 18432 + bbase + p * 2304 + ks * 32);
#pragma unroll
        for (int mi = 0; mi < 4; mi++) {
            uint32_t ah[4];
            ldm4(ah, sb + abase + mi * 2304 + ks * 32);
#pragma unroll
            for (int nt = 0; nt < 4; nt++) {
                int p = nt >> 1, j = nt & 1;
                mma_f16(acc[mi][nt], ah, bh[p][j], bh[p][j + 2]);
            }
        }
    }

    // staged epilogue: fp32 tile in smem (pitch 544B), then float4 streaming stores
    __syncthreads();
    const int g = lane >> 2, tg = lane & 3;
#pragma unroll
    for (int mi = 0; mi < 4; mi++)
#pragma unroll
        for (int nt = 0; nt < 4; nt++) {
            int row = m0 + mi * 16 + g;
            int col = n0 + nt * 8 + tg * 2;
            *(float2*)(sm + row * 544 + col * 4)       = make_float2(acc[mi][nt][0], acc[mi][nt][1]);
            *(float2*)(sm + (row + 8) * 544 + col * 4) = make_float2(acc[mi][nt][2], acc[mi][nt][3]);
        }
    __syncthreads();

#pragma unroll
    for (int q = 0; q < 16; q++) {
        int idx = t + q * 256;              // 0..4095
        int row = idx >> 5, c4 = (idx & 31) << 2;
        int gu = u0 + row, gi = i0 + c4;
        if (gu < UD) {
            float4 v = *(const float4*)(sm + row * 544 + c4 * 4);
            if (gi + 4 <= ID) {
                __stcs((float4*)(out + (size_t)gu * ID + gi), v);
            } else if (gi < ID) {
                float vv[4] = {v.x, v.y, v.z, v.w};
                for (int e = 0; e < ID - gi; e++) out[(size_t)gu * ID + gi + e] = vv[e];
            }
        }
    }
}

// ---------------- launch ----------------
extern "C" void kernel_launch(void* const* d_in, const int* in_sizes, int n_in,
                              void* d_out, int out_size) {
    const float* lambda_mat = (const float*)d_in[0];
    const float* user_sv    = (const float*)d_in[1];
    const float* item_sv    = (const float*)d_in[2];
    const float* adj_mat    = (const float*)d_in[3];
    const float* norm_adj   = (const float*)d_in[4];
    float* out = (float*)d_out;

    cudaFuncSetAttribute(k12_mma, cudaFuncAttributeMaxDynamicSharedMemorySize, 55296);
    cudaFuncSetAttribute(k3_mma, cudaFuncAttributeMaxDynamicSharedMemorySize, 69632);

    p_item<<<IPAD2 / 64, 256>>>(item_sv);
    p_user<<<UPAD2 / 64, 256>>>(user_sv);
    k12_mma<<<237 + 282, 256, 55296>>>(norm_adj, adj_mat);
    red_lr<<<((UPAD + IPAD) * 64 + 255) / 256, 256>>>(lambda_mat);
    k3_mma<<<dim3(79, 94), 256, 69632>>>(out);
}